// round 4
// baseline (speedup 1.0000x reference)
#include <cuda_runtime.h>
#include <cstdint>

#define B_WIN   4096
#define NTOK    49
#define DIMC    384
#define NH      12
#define HD      32
#define M_TOTAL (B_WIN * NTOK)     // 200704
#define KDIM    384
#define QK_SCALE 0.17677669529663687f

// ---------------- scratch (no cudaMalloc allowed) ----------------
__device__ float g_qkv[(size_t)M_TOTAL * 1152];   // ~925 MB
__device__ float g_att[(size_t)M_TOTAL * DIMC];   // ~308 MB (tf32-rounded by attn)
__device__ float g_xr[(size_t)M_TOTAL * KDIM];    // ~308 MB tf32-rounded x
__device__ float g_wqkv[1152 * KDIM];
__device__ float g_wproj[DIMC * KDIM];
__device__ float g_bias[NH * NTOK * NTOK];

// ---------------- helpers ----------------
__device__ __forceinline__ uint32_t f2tf(float f) {
    uint32_t r;
    asm("cvt.rna.tf32.f32 %0, %1;" : "=r"(r) : "f"(f));
    return r;
}
__device__ __forceinline__ void cpa16(float* smem, const float* g) {
    uint32_t s = (uint32_t)__cvta_generic_to_shared(smem);
    asm volatile("cp.async.cg.shared.global [%0], [%1], 16;\n" :: "r"(s), "l"(g));
}

// ---------------- pre-pass: round to tf32 (RNA) ----------------
// mode 0: x -> g_xr,  1: qkv_w -> g_wqkv,  2: proj_w -> g_wproj
__global__ void round_tf32_kernel(const float* __restrict__ src, int n4, int mode) {
    float* dst = (mode == 0) ? g_xr : (mode == 1) ? g_wqkv : g_wproj;
    int i = blockIdx.x * blockDim.x + threadIdx.x;
    if (i < n4) {
        float4 v = ((const float4*)src)[i];
        float4 o;
        o.x = __uint_as_float(f2tf(v.x));
        o.y = __uint_as_float(f2tf(v.y));
        o.z = __uint_as_float(f2tf(v.z));
        o.w = __uint_as_float(f2tf(v.w));
        ((float4*)dst)[i] = o;
    }
}

__global__ void bias_expand_kernel(const float* __restrict__ bt, const int* __restrict__ ri) {
    int h = blockIdx.x;
    for (int e = threadIdx.x; e < NTOK * NTOK; e += blockDim.x)
        g_bias[h * NTOK * NTOK + e] = bt[ri[e] * NH + h];
}

// ---------------- tf32 mma.sync GEMM: C[M,Nc] = A[M,K] @ W[Nc,K]^T + bias ----------------
// BM=128, BN=64, BK=32, 256 threads (8 warps 4x2), warp tile 32x32.
// Inputs pre-rounded to tf32 -> NO cvt in the hot loop (raw bit loads).
// cp.async double buffer, XOR-swizzled smem (48KB), 1 barrier per k-tile.
#define BM  128
#define BN  64
#define BK  32

__device__ __forceinline__ int sw_store(int row, int c4) {
    return row * 32 + ((c4 ^ (row & 7)) << 2);
}
__device__ __forceinline__ uint32_t sw_loadu(const uint32_t* buf, int row, int kc) {
    return buf[row * 32 + ((((kc >> 2)) ^ (row & 7)) << 2) + (kc & 3)];
}

__global__ __launch_bounds__(256, 3) void gemm_tf32_kernel(
    const float* __restrict__ bias, float* __restrict__ Cext, int Nc, int mode)
{
    const float* A = (mode == 0) ? g_xr : g_att;
    const float* W = (mode == 0) ? g_wqkv : g_wproj;
    float*       C = (mode == 0) ? g_qkv : Cext;

    __shared__ float As[2][BM * 32];   // 32KB
    __shared__ float Bs[2][BN * 32];   // 16KB -> 48KB total

    const int tid    = threadIdx.x;
    const int warp   = tid >> 5;
    const int lane   = tid & 31;
    const int g      = lane >> 2;
    const int tg     = lane & 3;
    const int warp_m = warp >> 1;
    const int warp_n = warp & 1;

    const size_t mbase = (size_t)blockIdx.y * BM;
    const size_t nbase = (size_t)blockIdx.x * BN;
    const int KT = KDIM / BK;          // 12

    const int lrow = tid >> 3;
    const int lc4  = tid & 7;

    float acc[2][4][4];
#pragma unroll
    for (int ma = 0; ma < 2; ma++)
#pragma unroll
        for (int na = 0; na < 4; na++)
#pragma unroll
            for (int i = 0; i < 4; i++) acc[ma][na][i] = 0.f;

    auto issue = [&](int t, int buf) {
        const float* Ag = A + (mbase + lrow) * KDIM + t * BK + lc4 * 4;
#pragma unroll
        for (int i = 0; i < 4; i++)
            cpa16(&As[buf][sw_store(lrow + i * 32, lc4)], Ag + (size_t)i * 32 * KDIM);
        const float* Wg = W + (nbase + lrow) * KDIM + t * BK + lc4 * 4;
#pragma unroll
        for (int i = 0; i < 2; i++)
            cpa16(&Bs[buf][sw_store(lrow + i * 32, lc4)], Wg + (size_t)i * 32 * KDIM);
        asm volatile("cp.async.commit_group;\n");
    };

    auto compute = [&](int cur) {
        const uint32_t* Ab = (const uint32_t*)As[cur];
        const uint32_t* Bb = (const uint32_t*)Bs[cur];
#pragma unroll
        for (int ks = 0; ks < 4; ks++) {
            const int kc = ks * 8 + tg;
            uint32_t a[2][4];
#pragma unroll
            for (int ma = 0; ma < 2; ma++) {
                const int r = warp_m * 32 + ma * 16 + g;
                a[ma][0] = sw_loadu(Ab, r,     kc);
                a[ma][1] = sw_loadu(Ab, r + 8, kc);
                a[ma][2] = sw_loadu(Ab, r,     kc + 4);
                a[ma][3] = sw_loadu(Ab, r + 8, kc + 4);
            }
#pragma unroll
            for (int na = 0; na < 4; na++) {
                const int rb = warp_n * 32 + na * 8 + g;
                uint32_t b0 = sw_loadu(Bb, rb, kc);
                uint32_t b1 = sw_loadu(Bb, rb, kc + 4);
#pragma unroll
                for (int ma = 0; ma < 2; ma++) {
                    asm volatile(
                        "mma.sync.aligned.m16n8k8.row.col.f32.tf32.tf32.f32 "
                        "{%0,%1,%2,%3}, {%4,%5,%6,%7}, {%8,%9}, {%0,%1,%2,%3};\n"
                        : "+f"(acc[ma][na][0]), "+f"(acc[ma][na][1]),
                          "+f"(acc[ma][na][2]), "+f"(acc[ma][na][3])
                        : "r"(a[ma][0]), "r"(a[ma][1]), "r"(a[ma][2]), "r"(a[ma][3]),
                          "r"(b0), "r"(b1));
                }
            }
        }
    };

    issue(0, 0);
#pragma unroll 1
    for (int t = 0; t < KT; t++) {
        asm volatile("cp.async.wait_group 0;\n" ::: "memory");
        __syncthreads();
        if (t + 1 < KT) issue(t + 1, (t + 1) & 1);
        compute(t & 1);
    }

    // epilogue
#pragma unroll
    for (int ma = 0; ma < 2; ma++) {
        const size_t r0 = mbase + warp_m * 32 + ma * 16 + g;
#pragma unroll
        for (int na = 0; na < 4; na++) {
            const size_t col = nbase + warp_n * 32 + na * 8 + tg * 2;
            float b0 = __ldg(&bias[col]), b1 = __ldg(&bias[col + 1]);
            *(float2*)&C[r0 * (size_t)Nc + col] =
                make_float2(acc[ma][na][0] + b0, acc[ma][na][1] + b1);
            *(float2*)&C[(r0 + 8) * (size_t)Nc + col] =
                make_float2(acc[ma][na][2] + b0, acc[ma][na][3] + b1);
        }
    }
}

// ---------------- per-(window, head) attention ----------------
// Logits live in padded smem (stride 53 -> conflict-free) to cut register
// pressure; output is tf32-rounded so proj GEMM needs no A pre-pass.
__global__ __launch_bounds__(64) void attn_kernel()
{
    __shared__ float k_s[NTOK][HD];
    __shared__ float v_s[NTOK][HD];
    __shared__ float s_s[NTOK][53];

    const int bid = blockIdx.x;
    const int b = bid / NH, h = bid % NH;
    const float* base = g_qkv + (size_t)b * NTOK * 1152;
    const int tid = threadIdx.x;

    for (int idx = tid; idx < NTOK * 8; idx += 64) {
        int j = idx >> 3, dd = idx & 7;
        const float4* kp = (const float4*)(base + (size_t)j * 1152 + 384 + h * HD);
        *((float4*)&k_s[j][dd * 4]) = kp[dd];
        const float4* vp = (const float4*)(base + (size_t)j * 1152 + 768 + h * HD);
        *((float4*)&v_s[j][dd * 4]) = vp[dd];
    }
    __syncthreads();

    if (tid < NTOK) {
        float q[HD];
        const float4* qp = (const float4*)(base + (size_t)tid * 1152 + h * HD);
#pragma unroll
        for (int d4 = 0; d4 < 8; d4++) {
            float4 t = qp[d4];
            q[d4 * 4 + 0] = t.x; q[d4 * 4 + 1] = t.y;
            q[d4 * 4 + 2] = t.z; q[d4 * 4 + 3] = t.w;
        }

        const float* gb = g_bias + h * (NTOK * NTOK) + tid * NTOK;
        float mx = -1e30f;
#pragma unroll
        for (int j = 0; j < NTOK; j++) {
            float acc = 0.f;
            const float4* kr = (const float4*)&k_s[j][0];
#pragma unroll
            for (int d4 = 0; d4 < 8; d4++) {
                float4 kv = kr[d4];
                acc += q[d4 * 4 + 0] * kv.x + q[d4 * 4 + 1] * kv.y
                     + q[d4 * 4 + 2] * kv.z + q[d4 * 4 + 3] * kv.w;
            }
            float val = acc * QK_SCALE + __ldg(&gb[j]);
            s_s[tid][j] = val;
            mx = fmaxf(mx, val);
        }

        float sum = 0.f;
#pragma unroll
        for (int j = 0; j < NTOK; j++) {
            float e = __expf(s_s[tid][j] - mx);
            s_s[tid][j] = e;
            sum += e;
        }
        float inv = 1.f / sum;

        float o[HD];
#pragma unroll
        for (int d = 0; d < HD; d++) o[d] = 0.f;
#pragma unroll
        for (int j = 0; j < NTOK; j++) {
            float p = s_s[tid][j];
            const float4* vr = (const float4*)&v_s[j][0];
#pragma unroll
            for (int d4 = 0; d4 < 8; d4++) {
                float4 vv = vr[d4];
                o[d4 * 4 + 0] += p * vv.x; o[d4 * 4 + 1] += p * vv.y;
                o[d4 * 4 + 2] += p * vv.z; o[d4 * 4 + 3] += p * vv.w;
            }
        }

        float* op = g_att + ((size_t)b * NTOK + tid) * DIMC + h * HD;
#pragma unroll
        for (int d4 = 0; d4 < 8; d4++)
            *((float4*)&op[d4 * 4]) = make_float4(
                __uint_as_float(f2tf(o[d4 * 4 + 0] * inv)),
                __uint_as_float(f2tf(o[d4 * 4 + 1] * inv)),
                __uint_as_float(f2tf(o[d4 * 4 + 2] * inv)),
                __uint_as_float(f2tf(o[d4 * 4 + 3] * inv)));
    }
}

// ---------------- launch ----------------
extern "C" void kernel_launch(void* const* d_in, const int* in_sizes, int n_in,
                              void* d_out, int out_size)
{
    const float* x      = (const float*)d_in[0];
    const float* qkv_w  = (const float*)d_in[1];
    const float* qkv_b  = (const float*)d_in[2];
    const float* proj_w = (const float*)d_in[3];
    const float* proj_b = (const float*)d_in[4];
    const float* bt     = (const float*)d_in[5];
    const int*   ri     = (const int*)d_in[6];
    float* out = (float*)d_out;

    bias_expand_kernel<<<NH, 256>>>(bt, ri);

    {
        int n4 = (M_TOTAL * KDIM) / 4;
        round_tf32_kernel<<<(n4 + 255) / 256, 256>>>(x, n4, 0);
    }
    {
        int n4 = (1152 * KDIM) / 4;
        round_tf32_kernel<<<(n4 + 255) / 256, 256>>>(qkv_w, n4, 1);
    }
    {
        int n4 = (DIMC * KDIM) / 4;
        round_tf32_kernel<<<(n4 + 255) / 256, 256>>>(proj_w, n4, 2);
    }

    dim3 gq(1152 / BN, M_TOTAL / BM);            // 18 x 1568
    gemm_tf32_kernel<<<gq, 256>>>(qkv_b, out, 1152, 0);

    attn_kernel<<<B_WIN * NH, 64>>>();

    dim3 gp(DIMC / BN, M_TOTAL / BM);            // 6 x 1568
    gemm_tf32_kernel<<<gp, 256>>>(proj_b, out, DIMC, 1);
}

// round 5
// speedup vs baseline: 1.3926x; 1.3926x over previous
#include <cuda_runtime.h>
#include <cstdint>

#define B_WIN   4096
#define NTOK    49
#define DIMC    384
#define NH      12
#define HD      32
#define M_TOTAL (B_WIN * NTOK)     // 200704
#define KDIM    384
#define QK_SCALE 0.17677669529663687f

// ---------------- scratch (no cudaMalloc allowed) ----------------
__device__ float g_qkv[(size_t)M_TOTAL * 1152];   // ~925 MB
__device__ float g_att[(size_t)M_TOTAL * DIMC];   // ~308 MB (tf32-rounded by attn)
__device__ float g_xr[(size_t)M_TOTAL * KDIM];    // ~308 MB tf32-rounded x
__device__ float g_wqkv[1152 * KDIM];
__device__ float g_wproj[DIMC * KDIM];
__device__ float g_bias[NH * NTOK * NTOK];

// ---------------- helpers ----------------
__device__ __forceinline__ uint32_t f2tf(float f) {
    uint32_t r;
    asm("cvt.rna.tf32.f32 %0, %1;" : "=r"(r) : "f"(f));
    return r;
}
__device__ __forceinline__ void cpa16(float* smem, const float* g) {
    uint32_t s = (uint32_t)__cvta_generic_to_shared(smem);
    asm volatile("cp.async.cg.shared.global [%0], [%1], 16;\n" :: "r"(s), "l"(g));
}

// ---------------- pre-pass: round to tf32 (RNA) ----------------
__global__ void round_tf32_kernel(const float* __restrict__ src, int n4, int mode) {
    float* dst = (mode == 0) ? g_xr : (mode == 1) ? g_wqkv : g_wproj;
    int i = blockIdx.x * blockDim.x + threadIdx.x;
    if (i < n4) {
        float4 v = ((const float4*)src)[i];
        float4 o;
        o.x = __uint_as_float(f2tf(v.x));
        o.y = __uint_as_float(f2tf(v.y));
        o.z = __uint_as_float(f2tf(v.z));
        o.w = __uint_as_float(f2tf(v.w));
        ((float4*)dst)[i] = o;
    }
}

__global__ void bias_expand_kernel(const float* __restrict__ bt, const int* __restrict__ ri) {
    int h = blockIdx.x;
    for (int e = threadIdx.x; e < NTOK * NTOK; e += blockDim.x)
        g_bias[h * NTOK * NTOK + e] = bt[ri[e] * NH + h];
}

// ---------------- tf32 mma.sync GEMM: C[M,Nc] = A[M,K] @ W[Nc,K]^T + bias ----------------
// BM=128, BN=64, BK=32, 256 threads (8 warps 4x2), warp tile 32x32.
// Inputs pre-rounded -> raw bit loads, zero cvt in hot loop.
// cp.async double buffer, XOR-swizzled smem (48KB), 1 barrier per k-tile.
#define BM  128
#define BN  64
#define BK  32

__device__ __forceinline__ int sw_store(int row, int c4) {
    return row * 32 + ((c4 ^ (row & 7)) << 2);
}
__device__ __forceinline__ uint32_t sw_loadu(const uint32_t* buf, int row, int kc) {
    return buf[row * 32 + ((((kc >> 2)) ^ (row & 7)) << 2) + (kc & 3)];
}

__global__ __launch_bounds__(256) void gemm_tf32_kernel(
    const float* __restrict__ bias, float* __restrict__ Cext, int Nc, int mode)
{
    const float* A = (mode == 0) ? g_xr : g_att;
    const float* W = (mode == 0) ? g_wqkv : g_wproj;
    float*       C = (mode == 0) ? g_qkv : Cext;

    __shared__ float As[2][BM * 32];   // 32KB
    __shared__ float Bs[2][BN * 32];   // 16KB -> 48KB total

    const int tid    = threadIdx.x;
    const int warp   = tid >> 5;
    const int lane   = tid & 31;
    const int g      = lane >> 2;
    const int tg     = lane & 3;
    const int warp_m = warp >> 1;
    const int warp_n = warp & 1;

    const size_t mbase = (size_t)blockIdx.y * BM;
    const size_t nbase = (size_t)blockIdx.x * BN;
    const int KT = KDIM / BK;          // 12

    const int lrow = tid >> 3;
    const int lc4  = tid & 7;

    float acc[2][4][4];
#pragma unroll
    for (int ma = 0; ma < 2; ma++)
#pragma unroll
        for (int na = 0; na < 4; na++)
#pragma unroll
            for (int i = 0; i < 4; i++) acc[ma][na][i] = 0.f;

    auto issue = [&](int t, int buf) {
        const float* Ag = A + (mbase + lrow) * KDIM + t * BK + lc4 * 4;
#pragma unroll
        for (int i = 0; i < 4; i++)
            cpa16(&As[buf][sw_store(lrow + i * 32, lc4)], Ag + (size_t)i * 32 * KDIM);
        const float* Wg = W + (nbase + lrow) * KDIM + t * BK + lc4 * 4;
#pragma unroll
        for (int i = 0; i < 2; i++)
            cpa16(&Bs[buf][sw_store(lrow + i * 32, lc4)], Wg + (size_t)i * 32 * KDIM);
        asm volatile("cp.async.commit_group;\n");
    };

    auto compute = [&](int cur) {
        const uint32_t* Ab = (const uint32_t*)As[cur];
        const uint32_t* Bb = (const uint32_t*)Bs[cur];
#pragma unroll
        for (int ks = 0; ks < 4; ks++) {
            const int kc = ks * 8 + tg;
            uint32_t a[2][4];
#pragma unroll
            for (int ma = 0; ma < 2; ma++) {
                const int r = warp_m * 32 + ma * 16 + g;
                a[ma][0] = sw_loadu(Ab, r,     kc);
                a[ma][1] = sw_loadu(Ab, r + 8, kc);
                a[ma][2] = sw_loadu(Ab, r,     kc + 4);
                a[ma][3] = sw_loadu(Ab, r + 8, kc + 4);
            }
#pragma unroll
            for (int na = 0; na < 4; na++) {
                const int rb = warp_n * 32 + na * 8 + g;
                uint32_t b0 = sw_loadu(Bb, rb, kc);
                uint32_t b1 = sw_loadu(Bb, rb, kc + 4);
#pragma unroll
                for (int ma = 0; ma < 2; ma++) {
                    asm volatile(
                        "mma.sync.aligned.m16n8k8.row.col.f32.tf32.tf32.f32 "
                        "{%0,%1,%2,%3}, {%4,%5,%6,%7}, {%8,%9}, {%0,%1,%2,%3};\n"
                        : "+f"(acc[ma][na][0]), "+f"(acc[ma][na][1]),
                          "+f"(acc[ma][na][2]), "+f"(acc[ma][na][3])
                        : "r"(a[ma][0]), "r"(a[ma][1]), "r"(a[ma][2]), "r"(a[ma][3]),
                          "r"(b0), "r"(b1));
                }
            }
        }
    };

    issue(0, 0);
#pragma unroll 1
    for (int t = 0; t < KT; t++) {
        asm volatile("cp.async.wait_group 0;\n" ::: "memory");
        __syncthreads();
        if (t + 1 < KT) issue(t + 1, (t + 1) & 1);
        compute(t & 1);
    }

    // epilogue
#pragma unroll
    for (int ma = 0; ma < 2; ma++) {
        const size_t r0 = mbase + warp_m * 32 + ma * 16 + g;
#pragma unroll
        for (int na = 0; na < 4; na++) {
            const size_t col = nbase + warp_n * 32 + na * 8 + tg * 2;
            float b0 = __ldg(&bias[col]), b1 = __ldg(&bias[col + 1]);
            *(float2*)&C[r0 * (size_t)Nc + col] =
                make_float2(acc[ma][na][0] + b0, acc[ma][na][1] + b1);
            *(float2*)&C[(r0 + 8) * (size_t)Nc + col] =
                make_float2(acc[ma][na][2] + b0, acc[ma][na][3] + b1);
        }
    }
}

// ---------------- per-(window, head) attention ----------------
// Register version (R2 layout). q prefetched before the K/V barrier.
// Output tf32-rounded so the proj GEMM can load raw bits.
__global__ __launch_bounds__(64) void attn_kernel()
{
    __shared__ float k_s[NTOK][HD];
    __shared__ float v_s[NTOK][HD];

    const int bid = blockIdx.x;
    const int b = bid / NH, h = bid % NH;
    const float* base = g_qkv + (size_t)b * NTOK * 1152;
    const int tid = threadIdx.x;

    // prefetch q (global) before the cooperative smem fill: overlaps latency
    float q[HD];
    if (tid < NTOK) {
        const float4* qp = (const float4*)(base + (size_t)tid * 1152 + h * HD);
#pragma unroll
        for (int d4 = 0; d4 < 8; d4++) {
            float4 t = qp[d4];
            q[d4 * 4 + 0] = t.x; q[d4 * 4 + 1] = t.y;
            q[d4 * 4 + 2] = t.z; q[d4 * 4 + 3] = t.w;
        }
    }

    for (int idx = tid; idx < NTOK * 8; idx += 64) {
        int j = idx >> 3, dd = idx & 7;
        const float4* kp = (const float4*)(base + (size_t)j * 1152 + 384 + h * HD);
        *((float4*)&k_s[j][dd * 4]) = kp[dd];
        const float4* vp = (const float4*)(base + (size_t)j * 1152 + 768 + h * HD);
        *((float4*)&v_s[j][dd * 4]) = vp[dd];
    }
    __syncthreads();

    if (tid < NTOK) {
        const float* gb = g_bias + h * (NTOK * NTOK) + tid * NTOK;
        float s[NTOK];
        float mx = -1e30f;
#pragma unroll
        for (int j = 0; j < NTOK; j++) {
            float acc = 0.f;
            const float4* kr = (const float4*)&k_s[j][0];
#pragma unroll
            for (int d4 = 0; d4 < 8; d4++) {
                float4 kv = kr[d4];
                acc += q[d4 * 4 + 0] * kv.x + q[d4 * 4 + 1] * kv.y
                     + q[d4 * 4 + 2] * kv.z + q[d4 * 4 + 3] * kv.w;
            }
            float val = acc * QK_SCALE + __ldg(&gb[j]);
            s[j] = val;
            mx = fmaxf(mx, val);
        }

        float sum = 0.f;
#pragma unroll
        for (int j = 0; j < NTOK; j++) {
            float e = __expf(s[j] - mx);
            s[j] = e;
            sum += e;
        }
        float inv = 1.f / sum;

        float o[HD];
#pragma unroll
        for (int d = 0; d < HD; d++) o[d] = 0.f;
#pragma unroll
        for (int j = 0; j < NTOK; j++) {
            float p = s[j];
            const float4* vr = (const float4*)&v_s[j][0];
#pragma unroll
            for (int d4 = 0; d4 < 8; d4++) {
                float4 vv = vr[d4];
                o[d4 * 4 + 0] += p * vv.x; o[d4 * 4 + 1] += p * vv.y;
                o[d4 * 4 + 2] += p * vv.z; o[d4 * 4 + 3] += p * vv.w;
            }
        }

        float* op = g_att + ((size_t)b * NTOK + tid) * DIMC + h * HD;
#pragma unroll
        for (int d4 = 0; d4 < 8; d4++)
            *((float4*)&op[d4 * 4]) = make_float4(
                __uint_as_float(f2tf(o[d4 * 4 + 0] * inv)),
                __uint_as_float(f2tf(o[d4 * 4 + 1] * inv)),
                __uint_as_float(f2tf(o[d4 * 4 + 2] * inv)),
                __uint_as_float(f2tf(o[d4 * 4 + 3] * inv)));
    }
}

// ---------------- launch ----------------
extern "C" void kernel_launch(void* const* d_in, const int* in_sizes, int n_in,
                              void* d_out, int out_size)
{
    const float* x      = (const float*)d_in[0];
    const float* qkv_w  = (const float*)d_in[1];
    const float* qkv_b  = (const float*)d_in[2];
    const float* proj_w = (const float*)d_in[3];
    const float* proj_b = (const float*)d_in[4];
    const float* bt     = (const float*)d_in[5];
    const int*   ri     = (const int*)d_in[6];
    float* out = (float*)d_out;

    bias_expand_kernel<<<NH, 256>>>(bt, ri);

    {
        int n4 = (M_TOTAL * KDIM) / 4;
        round_tf32_kernel<<<(n4 + 255) / 256, 256>>>(x, n4, 0);
    }
    {
        int n4 = (1152 * KDIM) / 4;
        round_tf32_kernel<<<(n4 + 255) / 256, 256>>>(qkv_w, n4, 1);
    }
    {
        int n4 = (DIMC * KDIM) / 4;
        round_tf32_kernel<<<(n4 + 255) / 256, 256>>>(proj_w, n4, 2);
    }

    dim3 gq(1152 / BN, M_TOTAL / BM);            // 18 x 1568
    gemm_tf32_kernel<<<gq, 256>>>(qkv_b, out, 1152, 0);

    attn_kernel<<<B_WIN * NH, 64>>>();

    dim3 gp(DIMC / BN, M_TOTAL / BM);            // 6 x 1568
    gemm_tf32_kernel<<<gp, 256>>>(proj_b, out, DIMC, 1);
}